// round 1
// baseline (speedup 1.0000x reference)
#include <cuda_runtime.h>
#include <math.h>

#define NB 16          // batch
#define NN 32767       // nodes = 2^15 - 1
#define HD 128         // hidden

__device__ __forceinline__ float sigm(float v) { return 1.f / (1.f + expf(-v)); }

// ============================================================================
// Init kernel: leaves only (indices 16383 .. 32766).
//   u = x[b,node] @ W_w + W_b  (K=128, N=256)
//   h = (1 - sigmoid(u[:128])) * tanh(u[128:])
// grid (256, 16), block 256. dyn smem = (64*132 + 32*256)*4 = 66560 B
// Thread (tm,tn) = 16x16 grid; rows tm*4+r, paired cols tn*8+c and 128+tn*8+c.
// ============================================================================
__global__ __launch_bounds__(256) void init_leaves_k(
    const float* __restrict__ x, const float* __restrict__ Ww,
    const float* __restrict__ Wb, float* __restrict__ h)
{
    extern __shared__ float sm[];
    float* xs = sm;              // [64][132] padded
    float* ws = sm + 64 * 132;   // [32][256]

    const int tid   = threadIdx.x;
    const int batch = blockIdx.y;
    const int row0  = blockIdx.x * 64;   // leaf-local row base

    // load x tile: 64 rows x 128 floats, contiguous leaf rows
    {
        const float* src = x + ((size_t)batch * NN + 16383 + row0) * HD;
        for (int i = tid; i < 64 * 32; i += 256) {
            int r = i >> 5, c = (i & 31) * 4;
            float4 v = *(const float4*)(src + r * HD + c);
            float* d = xs + r * 132 + c;
            d[0] = v.x; d[1] = v.y; d[2] = v.z; d[3] = v.w;
        }
    }

    const int tm = tid >> 4, tn = tid & 15;
    float acc[4][16];
#pragma unroll
    for (int r = 0; r < 4; r++)
#pragma unroll
        for (int c = 0; c < 16; c++) acc[r][c] = 0.f;

    for (int kc = 0; kc < 4; kc++) {
        __syncthreads();   // xs ready (first iter) / prior ws readers done
        for (int i = tid; i < 32 * 64; i += 256) {
            int r = i >> 6, c = (i & 63) * 4;
            float4 v = *(const float4*)(Ww + (size_t)(kc * 32 + r) * 256 + c);
            float* d = ws + r * 256 + c;
            d[0] = v.x; d[1] = v.y; d[2] = v.z; d[3] = v.w;
        }
        __syncthreads();
#pragma unroll 8
        for (int k = 0; k < 32; k++) {
            float a[4];
#pragma unroll
            for (int r = 0; r < 4; r++) a[r] = xs[(tm * 4 + r) * 132 + kc * 32 + k];
            const float4* w0 = (const float4*)(ws + k * 256 + tn * 8);
            const float4* w1 = (const float4*)(ws + k * 256 + 128 + tn * 8);
            float4 bA0 = w0[0], bA1 = w0[1], bB0 = w1[0], bB1 = w1[1];
#pragma unroll
            for (int r = 0; r < 4; r++) {
                acc[r][0]  += a[r] * bA0.x; acc[r][1]  += a[r] * bA0.y;
                acc[r][2]  += a[r] * bA0.z; acc[r][3]  += a[r] * bA0.w;
                acc[r][4]  += a[r] * bA1.x; acc[r][5]  += a[r] * bA1.y;
                acc[r][6]  += a[r] * bA1.z; acc[r][7]  += a[r] * bA1.w;
                acc[r][8]  += a[r] * bB0.x; acc[r][9]  += a[r] * bB0.y;
                acc[r][10] += a[r] * bB0.z; acc[r][11] += a[r] * bB0.w;
                acc[r][12] += a[r] * bB1.x; acc[r][13] += a[r] * bB1.y;
                acc[r][14] += a[r] * bB1.z; acc[r][15] += a[r] * bB1.w;
            }
        }
    }

#pragma unroll
    for (int r = 0; r < 4; r++) {
        int lrow = tm * 4 + r;
        size_t op = ((size_t)batch * NN + 16383 + row0 + lrow) * HD;
#pragma unroll
        for (int c = 0; c < 8; c++) {
            int j = tn * 8 + c;
            float f0 = sigm(acc[r][c] + Wb[j]);
            float c0 = tanhf(acc[r][8 + c] + Wb[128 + j]);
            h[op + j] = (1.f - f0) * c0;
        }
    }
}

// ============================================================================
// Big-level kernel (cnt >= 256, cnt % 64 == 0):
//   hc (64x256 contiguous in h) -> f=sigmoid(hc@Ufw+b) -> g=f*hc (in-place)
//   -> cand=tanh(g@Uhw+b) -> h_new = (1-fsum)*cand + gsum
// grid (cnt/64, 16), block 256. dyn smem = (64*260 + 64*128 + 32*256)*4 = 132096 B
// ============================================================================
__global__ __launch_bounds__(256) void level_big_k(
    const float* __restrict__ Ufw, const float* __restrict__ Ufb,
    const float* __restrict__ Uhw, const float* __restrict__ Uhb,
    float* __restrict__ h, int start)
{
    extern __shared__ float sm[];
    float* hc   = sm;                        // [64][260] hc, later g
    float* fsum = sm + 64 * 260;             // [64][128]
    float* ws   = sm + 64 * 260 + 64 * 128;  // [32][256]

    const int tid   = threadIdx.x;
    const int batch = blockIdx.y;
    const int node0 = start + blockIdx.x * 64;

    // hc tile: rows = concat(h[child 2i+1], h[child 2i+2]) -> 64x256 contiguous
    {
        const float* src = h + ((size_t)batch * NN + 2 * node0 + 1) * HD;
        for (int i = tid; i < 64 * 64; i += 256) {
            int r = i >> 6, c = (i & 63) * 4;
            float4 v = *(const float4*)(src + r * 256 + c);
            float* d = hc + r * 260 + c;
            d[0] = v.x; d[1] = v.y; d[2] = v.z; d[3] = v.w;
        }
    }

    const int tm = tid >> 4, tn = tid & 15;

    // ---- phase 1: u = hc @ Ufw (K=256, N=256), paired columns j / j+128 ----
    float acc[4][16];
#pragma unroll
    for (int r = 0; r < 4; r++)
#pragma unroll
        for (int c = 0; c < 16; c++) acc[r][c] = 0.f;

    for (int kc = 0; kc < 8; kc++) {
        __syncthreads();
        for (int i = tid; i < 32 * 64; i += 256) {
            int r = i >> 6, c = (i & 63) * 4;
            float4 v = *(const float4*)(Ufw + (size_t)(kc * 32 + r) * 256 + c);
            float* d = ws + r * 256 + c;
            d[0] = v.x; d[1] = v.y; d[2] = v.z; d[3] = v.w;
        }
        __syncthreads();
#pragma unroll 8
        for (int k = 0; k < 32; k++) {
            float a[4];
#pragma unroll
            for (int r = 0; r < 4; r++) a[r] = hc[(tm * 4 + r) * 260 + kc * 32 + k];
            const float4* w0 = (const float4*)(ws + k * 256 + tn * 8);
            const float4* w1 = (const float4*)(ws + k * 256 + 128 + tn * 8);
            float4 bA0 = w0[0], bA1 = w0[1], bB0 = w1[0], bB1 = w1[1];
#pragma unroll
            for (int r = 0; r < 4; r++) {
                acc[r][0]  += a[r] * bA0.x; acc[r][1]  += a[r] * bA0.y;
                acc[r][2]  += a[r] * bA0.z; acc[r][3]  += a[r] * bA0.w;
                acc[r][4]  += a[r] * bA1.x; acc[r][5]  += a[r] * bA1.y;
                acc[r][6]  += a[r] * bA1.z; acc[r][7]  += a[r] * bA1.w;
                acc[r][8]  += a[r] * bB0.x; acc[r][9]  += a[r] * bB0.y;
                acc[r][10] += a[r] * bB0.z; acc[r][11] += a[r] * bB0.w;
                acc[r][12] += a[r] * bB1.x; acc[r][13] += a[r] * bB1.y;
                acc[r][14] += a[r] * bB1.z; acc[r][15] += a[r] * bB1.w;
            }
        }
    }
    __syncthreads();   // all phase-1 reads of hc done before in-place g write

    // ---- epilogue 1: f = sigmoid(u+b); g = f*hc (overwrite hc); fsum ----
#pragma unroll
    for (int r = 0; r < 4; r++) {
        int lrow = tm * 4 + r;
#pragma unroll
        for (int c = 0; c < 8; c++) {
            int j = tn * 8 + c;
            float fA = sigm(acc[r][c] + Ufb[j]);
            float fB = sigm(acc[r][8 + c] + Ufb[128 + j]);
            float hA = hc[lrow * 260 + j];
            float hB = hc[lrow * 260 + 128 + j];
            hc[lrow * 260 + j]       = fA * hA;
            hc[lrow * 260 + 128 + j] = fB * hB;
            fsum[lrow * 128 + j]     = fA + fB;
        }
    }

    // ---- phase 2: v = g @ Uhw (K=256, N=128) ----
    float acc2[4][8];
#pragma unroll
    for (int r = 0; r < 4; r++)
#pragma unroll
        for (int c = 0; c < 8; c++) acc2[r][c] = 0.f;

    for (int kc = 0; kc < 8; kc++) {
        __syncthreads();   // also orders g/fsum writes before phase-2 reads
        for (int i = tid; i < 32 * 32; i += 256) {
            int r = i >> 5, c = (i & 31) * 4;
            float4 v = *(const float4*)(Uhw + (size_t)(kc * 32 + r) * 128 + c);
            float* d = ws + r * 128 + c;
            d[0] = v.x; d[1] = v.y; d[2] = v.z; d[3] = v.w;
        }
        __syncthreads();
#pragma unroll 8
        for (int k = 0; k < 32; k++) {
            float a[4];
#pragma unroll
            for (int r = 0; r < 4; r++) a[r] = hc[(tm * 4 + r) * 260 + kc * 32 + k];
            const float4* w = (const float4*)(ws + k * 128 + tn * 8);
            float4 b0 = w[0], b1 = w[1];
#pragma unroll
            for (int r = 0; r < 4; r++) {
                acc2[r][0] += a[r] * b0.x; acc2[r][1] += a[r] * b0.y;
                acc2[r][2] += a[r] * b0.z; acc2[r][3] += a[r] * b0.w;
                acc2[r][4] += a[r] * b1.x; acc2[r][5] += a[r] * b1.y;
                acc2[r][6] += a[r] * b1.z; acc2[r][7] += a[r] * b1.w;
            }
        }
    }

    // ---- epilogue 2 ----
#pragma unroll
    for (int r = 0; r < 4; r++) {
        int lrow = tm * 4 + r;
        size_t op = ((size_t)batch * NN + node0 + lrow) * HD;
#pragma unroll
        for (int c = 0; c < 8; c++) {
            int j = tn * 8 + c;
            float cand = tanhf(acc2[r][c] + Uhb[j]);
            float fsv  = fsum[lrow * 128 + j];
            float gsv  = hc[lrow * 260 + j] + hc[lrow * 260 + 128 + j];
            h[op + j] = (1.f - fsv) * cand + gsv;
        }
    }
}

// ============================================================================
// Small-level kernel (cnt < 256): one block per node, GEMV style.
// Weights read from global (384 KB total, stays hot in L1/L2).
// grid (cnt, 16), block 256.
// ============================================================================
__global__ __launch_bounds__(256) void level_small_k(
    const float* __restrict__ Ufw, const float* __restrict__ Ufb,
    const float* __restrict__ Uhw, const float* __restrict__ Uhb,
    float* __restrict__ h, int start)
{
    __shared__ float hcs[256];
    __shared__ float gs[256];
    __shared__ float fs[256];
    __shared__ float red[256];

    const int tid   = threadIdx.x;
    const int batch = blockIdx.y;
    const int node  = start + blockIdx.x;

    hcs[tid] = h[((size_t)batch * NN + 2 * node + 1) * HD + tid];
    __syncthreads();

    // phase 1: one output column per thread, 4-way k-split accumulators
    float a0 = 0.f, a1 = 0.f, a2 = 0.f, a3 = 0.f;
#pragma unroll 8
    for (int k = 0; k < 256; k += 4) {
        a0 += hcs[k]     * Ufw[(size_t)(k)     * 256 + tid];
        a1 += hcs[k + 1] * Ufw[(size_t)(k + 1) * 256 + tid];
        a2 += hcs[k + 2] * Ufw[(size_t)(k + 2) * 256 + tid];
        a3 += hcs[k + 3] * Ufw[(size_t)(k + 3) * 256 + tid];
    }
    float f = sigm((a0 + a1) + (a2 + a3) + Ufb[tid]);
    fs[tid] = f;
    gs[tid] = f * hcs[tid];
    __syncthreads();

    // phase 2: K split across two half-blocks, smem reduce
    const int j  = tid & 127;
    const int k0 = (tid >> 7) * 128;
    float b0 = 0.f, b1 = 0.f, b2 = 0.f, b3 = 0.f;
#pragma unroll 8
    for (int k = 0; k < 128; k += 4) {
        b0 += gs[k0 + k]     * Uhw[(size_t)(k0 + k)     * 128 + j];
        b1 += gs[k0 + k + 1] * Uhw[(size_t)(k0 + k + 1) * 128 + j];
        b2 += gs[k0 + k + 2] * Uhw[(size_t)(k0 + k + 2) * 128 + j];
        b3 += gs[k0 + k + 3] * Uhw[(size_t)(k0 + k + 3) * 128 + j];
    }
    red[tid] = (b0 + b1) + (b2 + b3);
    __syncthreads();

    if (tid < 128) {
        float cand = tanhf(red[tid] + red[tid + 128] + Uhb[tid]);
        float out  = (1.f - fs[tid] - fs[tid + 128]) * cand + gs[tid] + gs[tid + 128];
        h[((size_t)batch * NN + node) * HD + tid] = out;
    }
}

// ============================================================================
// Launch: 1 init + 14 level kernels. Level dependency is enforced by
// in-stream ordering (graph-capturable, no syncs, no allocations).
// ============================================================================
extern "C" void kernel_launch(void* const* d_in, const int* in_sizes, int n_in,
                              void* d_out, int out_size)
{
    const float* x   = (const float*)d_in[0];
    const float* Ww  = (const float*)d_in[1];
    const float* Wb  = (const float*)d_in[2];
    const float* Ufw = (const float*)d_in[3];
    const float* Ufb = (const float*)d_in[4];
    const float* Uhw = (const float*)d_in[5];
    const float* Uhb = (const float*)d_in[6];
    float* h = (float*)d_out;

    const int SM_INIT = (64 * 132 + 32 * 256) * 4;              // 66560 B
    const int SM_LVL  = (64 * 260 + 64 * 128 + 32 * 256) * 4;   // 132096 B
    cudaFuncSetAttribute(init_leaves_k, cudaFuncAttributeMaxDynamicSharedMemorySize, SM_INIT);
    cudaFuncSetAttribute(level_big_k,   cudaFuncAttributeMaxDynamicSharedMemorySize, SM_LVL);

    // leaves: 16384 per batch -> 256 x-blocks of 64 rows
    init_leaves_k<<<dim3(256, NB), 256, SM_INIT>>>(x, Ww, Wb, h);

    for (int l = 13; l >= 0; --l) {
        int start = (1 << l) - 1;
        int cnt   = 1 << l;
        if (cnt >= 256) {
            level_big_k<<<dim3(cnt / 64, NB), 256, SM_LVL>>>(Ufw, Ufb, Uhw, Uhb, h, start);
        } else {
            level_small_k<<<dim3(cnt, NB), 256>>>(Ufw, Ufb, Uhw, Uhb, h, start);
        }
    }
}

// round 2
// speedup vs baseline: 1.0006x; 1.0006x over previous
#include <cuda_runtime.h>
#include <math.h>

#define NB 16          // batch
#define NN 32767       // nodes = 2^15 - 1
#define HD 128         // hidden

__device__ __forceinline__ float sigm(float v) { return 1.f / (1.f + expf(-v)); }

// ============================================================================
// Init kernel: leaves only (indices 16383 .. 32766).
//   u = x[b,node] @ W_w + W_b  (K=128, N=256)
//   h = (1 - sigmoid(u[:128])) * tanh(u[128:])
// grid (256, 16), block 256. dyn smem = (64*132 + 32*256)*4 = 66560 B
// Thread (tm,tn) = 16x16 grid; rows tm*4+r, paired cols tn*8+c and 128+tn*8+c.
// ============================================================================
__global__ __launch_bounds__(256) void init_leaves_k(
    const float* __restrict__ x, const float* __restrict__ Ww,
    const float* __restrict__ Wb, float* __restrict__ h)
{
    extern __shared__ float sm[];
    float* xs = sm;              // [64][132] padded
    float* ws = sm + 64 * 132;   // [32][256]

    const int tid   = threadIdx.x;
    const int batch = blockIdx.y;
    const int row0  = blockIdx.x * 64;   // leaf-local row base

    // load x tile: 64 rows x 128 floats, contiguous leaf rows
    {
        const float* src = x + ((size_t)batch * NN + 16383 + row0) * HD;
        for (int i = tid; i < 64 * 32; i += 256) {
            int r = i >> 5, c = (i & 31) * 4;
            float4 v = *(const float4*)(src + r * HD + c);
            float* d = xs + r * 132 + c;
            d[0] = v.x; d[1] = v.y; d[2] = v.z; d[3] = v.w;
        }
    }

    const int tm = tid >> 4, tn = tid & 15;
    float acc[4][16];
#pragma unroll
    for (int r = 0; r < 4; r++)
#pragma unroll
        for (int c = 0; c < 16; c++) acc[r][c] = 0.f;

    for (int kc = 0; kc < 4; kc++) {
        __syncthreads();   // xs ready (first iter) / prior ws readers done
        for (int i = tid; i < 32 * 64; i += 256) {
            int r = i >> 6, c = (i & 63) * 4;
            float4 v = *(const float4*)(Ww + (size_t)(kc * 32 + r) * 256 + c);
            float* d = ws + r * 256 + c;
            d[0] = v.x; d[1] = v.y; d[2] = v.z; d[3] = v.w;
        }
        __syncthreads();
#pragma unroll 8
        for (int k = 0; k < 32; k++) {
            float a[4];
#pragma unroll
            for (int r = 0; r < 4; r++) a[r] = xs[(tm * 4 + r) * 132 + kc * 32 + k];
            const float4* w0 = (const float4*)(ws + k * 256 + tn * 8);
            const float4* w1 = (const float4*)(ws + k * 256 + 128 + tn * 8);
            float4 bA0 = w0[0], bA1 = w0[1], bB0 = w1[0], bB1 = w1[1];
#pragma unroll
            for (int r = 0; r < 4; r++) {
                acc[r][0]  += a[r] * bA0.x; acc[r][1]  += a[r] * bA0.y;
                acc[r][2]  += a[r] * bA0.z; acc[r][3]  += a[r] * bA0.w;
                acc[r][4]  += a[r] * bA1.x; acc[r][5]  += a[r] * bA1.y;
                acc[r][6]  += a[r] * bA1.z; acc[r][7]  += a[r] * bA1.w;
                acc[r][8]  += a[r] * bB0.x; acc[r][9]  += a[r] * bB0.y;
                acc[r][10] += a[r] * bB0.z; acc[r][11] += a[r] * bB0.w;
                acc[r][12] += a[r] * bB1.x; acc[r][13] += a[r] * bB1.y;
                acc[r][14] += a[r] * bB1.z; acc[r][15] += a[r] * bB1.w;
            }
        }
    }

#pragma unroll
    for (int r = 0; r < 4; r++) {
        int lrow = tm * 4 + r;
        size_t op = ((size_t)batch * NN + 16383 + row0 + lrow) * HD;
#pragma unroll
        for (int c = 0; c < 8; c++) {
            int j = tn * 8 + c;
            float f0 = sigm(acc[r][c] + Wb[j]);
            float c0 = tanhf(acc[r][8 + c] + Wb[128 + j]);
            h[op + j] = (1.f - f0) * c0;
        }
    }
}

// ============================================================================
// Big-level kernel (cnt >= 256, cnt % 64 == 0):
//   hc (64x256 contiguous in h) -> f=sigmoid(hc@Ufw+b) -> g=f*hc (in-place)
//   -> cand=tanh(g@Uhw+b) -> h_new = (1-fsum)*cand + gsum
// grid (cnt/64, 16), block 256. dyn smem = (64*260 + 64*128 + 32*256)*4 = 132096 B
// ============================================================================
__global__ __launch_bounds__(256) void level_big_k(
    const float* __restrict__ Ufw, const float* __restrict__ Ufb,
    const float* __restrict__ Uhw, const float* __restrict__ Uhb,
    float* __restrict__ h, int start)
{
    extern __shared__ float sm[];
    float* hc   = sm;                        // [64][260] hc, later g
    float* fsum = sm + 64 * 260;             // [64][128]
    float* ws   = sm + 64 * 260 + 64 * 128;  // [32][256]

    const int tid   = threadIdx.x;
    const int batch = blockIdx.y;
    const int node0 = start + blockIdx.x * 64;

    // hc tile: rows = concat(h[child 2i+1], h[child 2i+2]) -> 64x256 contiguous
    {
        const float* src = h + ((size_t)batch * NN + 2 * node0 + 1) * HD;
        for (int i = tid; i < 64 * 64; i += 256) {
            int r = i >> 6, c = (i & 63) * 4;
            float4 v = *(const float4*)(src + r * 256 + c);
            float* d = hc + r * 260 + c;
            d[0] = v.x; d[1] = v.y; d[2] = v.z; d[3] = v.w;
        }
    }

    const int tm = tid >> 4, tn = tid & 15;

    // ---- phase 1: u = hc @ Ufw (K=256, N=256), paired columns j / j+128 ----
    float acc[4][16];
#pragma unroll
    for (int r = 0; r < 4; r++)
#pragma unroll
        for (int c = 0; c < 16; c++) acc[r][c] = 0.f;

    for (int kc = 0; kc < 8; kc++) {
        __syncthreads();
        for (int i = tid; i < 32 * 64; i += 256) {
            int r = i >> 6, c = (i & 63) * 4;
            float4 v = *(const float4*)(Ufw + (size_t)(kc * 32 + r) * 256 + c);
            float* d = ws + r * 256 + c;
            d[0] = v.x; d[1] = v.y; d[2] = v.z; d[3] = v.w;
        }
        __syncthreads();
#pragma unroll 8
        for (int k = 0; k < 32; k++) {
            float a[4];
#pragma unroll
            for (int r = 0; r < 4; r++) a[r] = hc[(tm * 4 + r) * 260 + kc * 32 + k];
            const float4* w0 = (const float4*)(ws + k * 256 + tn * 8);
            const float4* w1 = (const float4*)(ws + k * 256 + 128 + tn * 8);
            float4 bA0 = w0[0], bA1 = w0[1], bB0 = w1[0], bB1 = w1[1];
#pragma unroll
            for (int r = 0; r < 4; r++) {
                acc[r][0]  += a[r] * bA0.x; acc[r][1]  += a[r] * bA0.y;
                acc[r][2]  += a[r] * bA0.z; acc[r][3]  += a[r] * bA0.w;
                acc[r][4]  += a[r] * bA1.x; acc[r][5]  += a[r] * bA1.y;
                acc[r][6]  += a[r] * bA1.z; acc[r][7]  += a[r] * bA1.w;
                acc[r][8]  += a[r] * bB0.x; acc[r][9]  += a[r] * bB0.y;
                acc[r][10] += a[r] * bB0.z; acc[r][11] += a[r] * bB0.w;
                acc[r][12] += a[r] * bB1.x; acc[r][13] += a[r] * bB1.y;
                acc[r][14] += a[r] * bB1.z; acc[r][15] += a[r] * bB1.w;
            }
        }
    }
    __syncthreads();   // all phase-1 reads of hc done before in-place g write

    // ---- epilogue 1: f = sigmoid(u+b); g = f*hc (overwrite hc); fsum ----
#pragma unroll
    for (int r = 0; r < 4; r++) {
        int lrow = tm * 4 + r;
#pragma unroll
        for (int c = 0; c < 8; c++) {
            int j = tn * 8 + c;
            float fA = sigm(acc[r][c] + Ufb[j]);
            float fB = sigm(acc[r][8 + c] + Ufb[128 + j]);
            float hA = hc[lrow * 260 + j];
            float hB = hc[lrow * 260 + 128 + j];
            hc[lrow * 260 + j]       = fA * hA;
            hc[lrow * 260 + 128 + j] = fB * hB;
            fsum[lrow * 128 + j]     = fA + fB;
        }
    }

    // ---- phase 2: v = g @ Uhw (K=256, N=128) ----
    float acc2[4][8];
#pragma unroll
    for (int r = 0; r < 4; r++)
#pragma unroll
        for (int c = 0; c < 8; c++) acc2[r][c] = 0.f;

    for (int kc = 0; kc < 8; kc++) {
        __syncthreads();   // also orders g/fsum writes before phase-2 reads
        for (int i = tid; i < 32 * 32; i += 256) {
            int r = i >> 5, c = (i & 31) * 4;
            float4 v = *(const float4*)(Uhw + (size_t)(kc * 32 + r) * 128 + c);
            float* d = ws + r * 128 + c;
            d[0] = v.x; d[1] = v.y; d[2] = v.z; d[3] = v.w;
        }
        __syncthreads();
#pragma unroll 8
        for (int k = 0; k < 32; k++) {
            float a[4];
#pragma unroll
            for (int r = 0; r < 4; r++) a[r] = hc[(tm * 4 + r) * 260 + kc * 32 + k];
            const float4* w = (const float4*)(ws + k * 128 + tn * 8);
            float4 b0 = w[0], b1 = w[1];
#pragma unroll
            for (int r = 0; r < 4; r++) {
                acc2[r][0] += a[r] * b0.x; acc2[r][1] += a[r] * b0.y;
                acc2[r][2] += a[r] * b0.z; acc2[r][3] += a[r] * b0.w;
                acc2[r][4] += a[r] * b1.x; acc2[r][5] += a[r] * b1.y;
                acc2[r][6] += a[r] * b1.z; acc2[r][7] += a[r] * b1.w;
            }
        }
    }

    // ---- epilogue 2 ----
#pragma unroll
    for (int r = 0; r < 4; r++) {
        int lrow = tm * 4 + r;
        size_t op = ((size_t)batch * NN + node0 + lrow) * HD;
#pragma unroll
        for (int c = 0; c < 8; c++) {
            int j = tn * 8 + c;
            float cand = tanhf(acc2[r][c] + Uhb[j]);
            float fsv  = fsum[lrow * 128 + j];
            float gsv  = hc[lrow * 260 + j] + hc[lrow * 260 + 128 + j];
            h[op + j] = (1.f - fsv) * cand + gsv;
        }
    }
}

// ============================================================================
// Small-level kernel (cnt < 256): one block per node, GEMV style.
// Weights read from global (384 KB total, stays hot in L1/L2).
// grid (cnt, 16), block 256.
// ============================================================================
__global__ __launch_bounds__(256) void level_small_k(
    const float* __restrict__ Ufw, const float* __restrict__ Ufb,
    const float* __restrict__ Uhw, const float* __restrict__ Uhb,
    float* __restrict__ h, int start)
{
    __shared__ float hcs[256];
    __shared__ float gs[256];
    __shared__ float fs[256];
    __shared__ float red[256];

    const int tid   = threadIdx.x;
    const int batch = blockIdx.y;
    const int node  = start + blockIdx.x;

    hcs[tid] = h[((size_t)batch * NN + 2 * node + 1) * HD + tid];
    __syncthreads();

    // phase 1: one output column per thread, 4-way k-split accumulators
    float a0 = 0.f, a1 = 0.f, a2 = 0.f, a3 = 0.f;
#pragma unroll 8
    for (int k = 0; k < 256; k += 4) {
        a0 += hcs[k]     * Ufw[(size_t)(k)     * 256 + tid];
        a1 += hcs[k + 1] * Ufw[(size_t)(k + 1) * 256 + tid];
        a2 += hcs[k + 2] * Ufw[(size_t)(k + 2) * 256 + tid];
        a3 += hcs[k + 3] * Ufw[(size_t)(k + 3) * 256 + tid];
    }
    float f = sigm((a0 + a1) + (a2 + a3) + Ufb[tid]);
    fs[tid] = f;
    gs[tid] = f * hcs[tid];
    __syncthreads();

    // phase 2: K split across two half-blocks, smem reduce
    const int j  = tid & 127;
    const int k0 = (tid >> 7) * 128;
    float b0 = 0.f, b1 = 0.f, b2 = 0.f, b3 = 0.f;
#pragma unroll 8
    for (int k = 0; k < 128; k += 4) {
        b0 += gs[k0 + k]     * Uhw[(size_t)(k0 + k)     * 128 + j];
        b1 += gs[k0 + k + 1] * Uhw[(size_t)(k0 + k + 1) * 128 + j];
        b2 += gs[k0 + k + 2] * Uhw[(size_t)(k0 + k + 2) * 128 + j];
        b3 += gs[k0 + k + 3] * Uhw[(size_t)(k0 + k + 3) * 128 + j];
    }
    red[tid] = (b0 + b1) + (b2 + b3);
    __syncthreads();

    if (tid < 128) {
        float cand = tanhf(red[tid] + red[tid + 128] + Uhb[tid]);
        float out  = (1.f - fs[tid] - fs[tid + 128]) * cand + gs[tid] + gs[tid + 128];
        h[((size_t)batch * NN + node) * HD + tid] = out;
    }
}

// ============================================================================
// Launch: 1 init + 14 level kernels. Level dependency is enforced by
// in-stream ordering (graph-capturable, no syncs, no allocations).
// ============================================================================
extern "C" void kernel_launch(void* const* d_in, const int* in_sizes, int n_in,
                              void* d_out, int out_size)
{
    const float* x   = (const float*)d_in[0];
    const float* Ww  = (const float*)d_in[1];
    const float* Wb  = (const float*)d_in[2];
    const float* Ufw = (const float*)d_in[3];
    const float* Ufb = (const float*)d_in[4];
    const float* Uhw = (const float*)d_in[5];
    const float* Uhb = (const float*)d_in[6];
    float* h = (float*)d_out;

    const int SM_INIT = (64 * 132 + 32 * 256) * 4;              // 66560 B
    const int SM_LVL  = (64 * 260 + 64 * 128 + 32 * 256) * 4;   // 132096 B
    cudaFuncSetAttribute(init_leaves_k, cudaFuncAttributeMaxDynamicSharedMemorySize, SM_INIT);
    cudaFuncSetAttribute(level_big_k,   cudaFuncAttributeMaxDynamicSharedMemorySize, SM_LVL);

    // leaves: 16384 per batch -> 256 x-blocks of 64 rows
    init_leaves_k<<<dim3(256, NB), 256, SM_INIT>>>(x, Ww, Wb, h);

    for (int l = 13; l >= 0; --l) {
        int start = (1 << l) - 1;
        int cnt   = 1 << l;
        if (cnt >= 256) {
            level_big_k<<<dim3(cnt / 64, NB), 256, SM_LVL>>>(Ufw, Ufb, Uhw, Uhb, h, start);
        } else {
            level_small_k<<<dim3(cnt, NB), 256>>>(Ufw, Ufb, Uhw, Uhb, h, start);
        }
    }
}

// round 5
// speedup vs baseline: 2.2064x; 2.2051x over previous
#include <cuda_runtime.h>
#include <math.h>
#include <stdint.h>

#define NB 16
#define NN 32767
#define HD 128

// tf32-rounded weight copies
__device__ float d_Uf[256 * 256];   // Ufw [k][n]
__device__ float d_Uh[256 * 128];   // Uhw [k][n]
__device__ float d_W0[128 * 256];   // Ww  [k][n]

__device__ __forceinline__ float sigm(float v) { return 1.f / (1.f + expf(-v)); }
__device__ __forceinline__ float tf32r(float x) {
    float r; asm("cvt.rna.tf32.f32 %0, %1;" : "=f"(r) : "f"(x)); return r;
}
__device__ __forceinline__ uint32_t smem_u32(const void* p) {
    uint32_t a;
    asm("{ .reg .u64 t; cvta.to.shared.u64 t, %1; cvt.u32.u64 %0, t; }" : "=r"(a) : "l"(p));
    return a;
}
__device__ __forceinline__ void mma8(float* d, const uint32_t* a, const uint32_t* b) {
    asm volatile(
        "mma.sync.aligned.m16n8k8.row.col.f32.tf32.tf32.f32 "
        "{%0,%1,%2,%3}, {%4,%5,%6,%7}, {%8,%9}, {%0,%1,%2,%3};"
        : "+f"(d[0]), "+f"(d[1]), "+f"(d[2]), "+f"(d[3])
        : "r"(a[0]), "r"(a[1]), "r"(a[2]), "r"(a[3]), "r"(b[0]), "r"(b[1]));
}
#define CP16(daddr, sptr) \
    asm volatile("cp.async.cg.shared.global [%0], [%1], 16;" :: "r"(daddr), "l"(sptr))
#define CP_COMMIT() asm volatile("cp.async.commit_group;" ::: "memory")
#define CP_WAIT1()  asm volatile("cp.async.wait_group 1;" ::: "memory")
#define CP_WAIT0()  asm volatile("cp.async.wait_group 0;" ::: "memory")

// strides (words)
#define AS 260      // level A tile [64][256] padded
#define US 260      // u / fsum / gsum staging
#define BS1 264     // B chunk [32][256] padded
#define BS2 136     // B chunk [32][128] padded
#define AIS 132     // init A tile [64][128] padded

// level smem (floats): sA 16640 | sU 16640 | sB 2*8448
#define L_SU 16640
#define L_SB 33280
#define SMEM_LVL ((16640 + 16640 + 2 * 8448) * 4)   // 200704 B
// init smem: sA 8448 | sU 16640 | sB 2*8448
#define I_SU 8448
#define I_SB 25088
#define SMEM_INI ((8448 + 16640 + 2 * 8448) * 4)    // 167936 B

// --------------------------------------------------------------------------
__global__ void prep_k(const float* __restrict__ Ww, const float* __restrict__ Ufw,
                       const float* __restrict__ Uhw)
{
    int i0 = blockIdx.x * blockDim.x + threadIdx.x, st = gridDim.x * blockDim.x;
    for (int idx = i0; idx < 131072; idx += st) {
        if (idx < 65536)        d_Uf[idx]         = tf32r(Ufw[idx]);
        else if (idx < 98304)   d_Uh[idx - 65536] = tf32r(Uhw[idx - 65536]);
        else                    d_W0[idx - 98304] = tf32r(Ww[idx - 98304]);
    }
}

// --------------------------------------------------------------------------
// Level kernel: 64 parent nodes per CTA, 256 threads (8 warps).
// Phase1: u[64][256] = hc @ Ufw ; Phase2: v[64][128] = g @ Uhw
// --------------------------------------------------------------------------
__global__ __launch_bounds__(256, 1) void level_mma_k(
    const float* __restrict__ Ufb, const float* __restrict__ Uhb,
    float* __restrict__ h, int start)
{
    extern __shared__ float sm[];
    float* sA = sm;
    float* sU = sm + L_SU;
    float* sB = sm + L_SB;
    const uint32_t sBa = smem_u32(sB);

    const int tid = threadIdx.x, lane = tid & 31, wid = tid >> 5;
    const int batch = blockIdx.y;
    const int node0 = start + blockIdx.x * 64;
    const float* hcg = h + ((size_t)batch * NN + 2 * node0 + 1) * HD;

    // prefetch B1 chunk 0
    for (int i = tid; i < 2048; i += 256) {
        int rw = i >> 6, c4 = (i & 63) << 2;
        CP16(sBa + (uint32_t)(rw * BS1 + c4) * 4u, d_Uf + rw * 256 + c4);
    }
    CP_COMMIT();

    // load A = hc tile (64 rows x 256), tf32-rounded
    for (int i = tid; i < 4096; i += 256) {
        float4 v = ((const float4*)hcg)[i];
        int r = i >> 6, c = (i & 63) << 2;
        float4 o = make_float4(tf32r(v.x), tf32r(v.y), tf32r(v.z), tf32r(v.w));
        *(float4*)(sA + r * AS + c) = o;
    }

    const int wm = wid & 1, wn = wid >> 1;
    const int wr = wm * 32;
    const int fr = lane >> 2, fc = lane & 3;
    const uint32_t* ap = (const uint32_t*)sA;

    // ---------------- phase 1 ----------------
    float acc[2][8][4];
#pragma unroll
    for (int mt = 0; mt < 2; mt++)
#pragma unroll
        for (int nt = 0; nt < 8; nt++)
#pragma unroll
            for (int q = 0; q < 4; q++) acc[mt][nt][q] = 0.f;

    for (int kc = 0; kc < 8; kc++) {
        if (kc + 1 < 8) {
            uint32_t dst = sBa + ((kc + 1) & 1) * 8448u * 4u;
            const float* src = d_Uf + (kc + 1) * 32 * 256;
            for (int i = tid; i < 2048; i += 256) {
                int rw = i >> 6, c4 = (i & 63) << 2;
                CP16(dst + (uint32_t)(rw * BS1 + c4) * 4u, src + rw * 256 + c4);
            }
            CP_COMMIT();
            CP_WAIT1();
        } else {
            CP_WAIT0();
        }
        __syncthreads();
        const uint32_t* bp = (const uint32_t*)(sB + (kc & 1) * 8448);
        const int wcb = wn * 64;
        const int ka = kc * 32;                 // A K-chunk base (the R4 bug fix)
#pragma unroll
        for (int ks = 0; ks < 4; ks++) {
            const int kk = ks * 8;
            uint32_t a[2][4];
#pragma unroll
            for (int mt = 0; mt < 2; mt++) {
                int rb = (wr + mt * 16 + fr) * AS + ka + kk + fc;
                a[mt][0] = ap[rb];
                a[mt][1] = ap[rb + 8 * AS];
                a[mt][2] = ap[rb + 4];
                a[mt][3] = ap[rb + 8 * AS + 4];
            }
#pragma unroll
            for (int nt = 0; nt < 8; nt++) {
                uint32_t b[2];
                int bb = (kk + fc) * BS1 + wcb + nt * 8 + fr;
                b[0] = bp[bb];
                b[1] = bp[bb + 4 * BS1];
#pragma unroll
                for (int mt = 0; mt < 2; mt++) mma8(acc[mt][nt], a[mt], b);
            }
        }
        __syncthreads();
    }

    // stage u into sU
#pragma unroll
    for (int mt = 0; mt < 2; mt++)
#pragma unroll
        for (int nt = 0; nt < 8; nt++) {
            int row = wr + mt * 16 + fr;
            int col = wn * 64 + nt * 8 + 2 * fc;
            *(float2*)(sU + row * US + col) = make_float2(acc[mt][nt][0], acc[mt][nt][1]);
            *(float2*)(sU + (row + 8) * US + col) = make_float2(acc[mt][nt][2], acc[mt][nt][3]);
        }
    __syncthreads();

    // prefetch B2 chunk 0 (overlaps epilogue 1)
    for (int i = tid; i < 1024; i += 256) {
        int rw = i >> 5, c4 = (i & 31) << 2;
        CP16(sBa + (uint32_t)(rw * BS2 + c4) * 4u, d_Uh + rw * 128 + c4);
    }
    CP_COMMIT();

    // ---------------- epilogue 1 ----------------
    // f from u; g = f * hc(exact, re-read) -> sA (tf32); fsum -> sU[:,j]; gsum -> sU[:,j+128]
    for (int i = tid; i < 64 * 128; i += 256) {
        int rr = i >> 7, j = i & 127;
        float uA = sU[rr * US + j], uB = sU[rr * US + j + 128];
        float fA = sigm(uA + __ldg(Ufb + j));
        float fB = sigm(uB + __ldg(Ufb + 128 + j));
        float hA = __ldg(hcg + rr * 256 + j);
        float hB = __ldg(hcg + rr * 256 + 128 + j);
        float gA = fA * hA, gB = fB * hB;
        sA[rr * AS + j]       = tf32r(gA);
        sA[rr * AS + j + 128] = tf32r(gB);
        sU[rr * US + j]       = fA + fB;   // fsum
        sU[rr * US + j + 128] = gA + gB;   // gsum (exact fp32)
    }
    __syncthreads();

    // ---------------- phase 2 ----------------
    float ac2[2][4][4];
#pragma unroll
    for (int mt = 0; mt < 2; mt++)
#pragma unroll
        for (int nt = 0; nt < 4; nt++)
#pragma unroll
            for (int q = 0; q < 4; q++) ac2[mt][nt][q] = 0.f;

    for (int kc = 0; kc < 8; kc++) {
        if (kc + 1 < 8) {
            uint32_t dst = sBa + ((kc + 1) & 1) * 8448u * 4u;
            const float* src = d_Uh + (kc + 1) * 32 * 128;
            for (int i = tid; i < 1024; i += 256) {
                int rw = i >> 5, c4 = (i & 31) << 2;
                CP16(dst + (uint32_t)(rw * BS2 + c4) * 4u, src + rw * 128 + c4);
            }
            CP_COMMIT();
            CP_WAIT1();
        } else {
            CP_WAIT0();
        }
        __syncthreads();
        const uint32_t* bp = (const uint32_t*)(sB + (kc & 1) * 8448);
        const int wcb = wn * 32;
        const int ka = kc * 32;                 // A K-chunk base (fix)
#pragma unroll
        for (int ks = 0; ks < 4; ks++) {
            const int kk = ks * 8;
            uint32_t a[2][4];
#pragma unroll
            for (int mt = 0; mt < 2; mt++) {
                int rb = (wr + mt * 16 + fr) * AS + ka + kk + fc;
                a[mt][0] = ap[rb];
                a[mt][1] = ap[rb + 8 * AS];
                a[mt][2] = ap[rb + 4];
                a[mt][3] = ap[rb + 8 * AS + 4];
            }
#pragma unroll
            for (int nt = 0; nt < 4; nt++) {
                uint32_t b[2];
                int bb = (kk + fc) * BS2 + wcb + nt * 8 + fr;
                b[0] = bp[bb];
                b[1] = bp[bb + 4 * BS2];
#pragma unroll
                for (int mt = 0; mt < 2; mt++) mma8(ac2[mt][nt], a[mt], b);
            }
        }
        __syncthreads();
    }

    // ---------------- epilogue 2 ----------------
#pragma unroll
    for (int mt = 0; mt < 2; mt++)
#pragma unroll
        for (int nt = 0; nt < 4; nt++) {
            int lr0 = wr + mt * 16 + fr;
            int lr1 = lr0 + 8;
            int col = wn * 32 + nt * 8 + 2 * fc;
            float bh0 = __ldg(Uhb + col), bh1 = __ldg(Uhb + col + 1);
            const float* a = ac2[mt][nt];
            float o00 = (1.f - sU[lr0 * US + col])     * tanhf(a[0] + bh0) + sU[lr0 * US + col + 128];
            float o01 = (1.f - sU[lr0 * US + col + 1]) * tanhf(a[1] + bh1) + sU[lr0 * US + col + 129];
            float o10 = (1.f - sU[lr1 * US + col])     * tanhf(a[2] + bh0) + sU[lr1 * US + col + 128];
            float o11 = (1.f - sU[lr1 * US + col + 1]) * tanhf(a[3] + bh1) + sU[lr1 * US + col + 129];
            float* outp = h + ((size_t)batch * NN + node0 + lr0) * HD + col;
            *(float2*)outp = make_float2(o00, o01);
            *(float2*)(outp + 8 * HD) = make_float2(o10, o11);
        }
}

// --------------------------------------------------------------------------
// Init kernel: 64 leaf rows per CTA. u = x @ Ww (K=128, N=256) + elementwise.
// --------------------------------------------------------------------------
__global__ __launch_bounds__(256, 1) void init_mma_k(
    const float* __restrict__ x, const float* __restrict__ Wb, float* __restrict__ h)
{
    extern __shared__ float sm[];
    float* sA = sm;
    float* sU = sm + I_SU;
    float* sB = sm + I_SB;
    const uint32_t sBa = smem_u32(sB);

    const int tid = threadIdx.x, lane = tid & 31, wid = tid >> 5;
    const int batch = blockIdx.y;
    const int row0 = blockIdx.x * 64;   // leaf-local
    const float* xg = x + ((size_t)batch * NN + 16383 + row0) * HD;

    // prefetch W chunk 0: [32][256] = 2048 float4  (R4 bug fix: full chunk)
    for (int i = tid; i < 2048; i += 256) {
        int rw = i >> 6, c4 = (i & 63) << 2;
        CP16(sBa + (uint32_t)(rw * BS1 + c4) * 4u, d_W0 + rw * 256 + c4);
    }
    CP_COMMIT();

    for (int i = tid; i < 2048; i += 256) {
        float4 v = ((const float4*)xg)[i];
        int r = i >> 5, c = (i & 31) << 2;
        float4 o = make_float4(tf32r(v.x), tf32r(v.y), tf32r(v.z), tf32r(v.w));
        *(float4*)(sA + r * AIS + c) = o;
    }

    const int wm = wid & 1, wn = wid >> 1;
    const int wr = wm * 32;
    const int fr = lane >> 2, fc = lane & 3;
    const uint32_t* ap = (const uint32_t*)sA;

    float acc[2][8][4];
#pragma unroll
    for (int mt = 0; mt < 2; mt++)
#pragma unroll
        for (int nt = 0; nt < 8; nt++)
#pragma unroll
            for (int q = 0; q < 4; q++) acc[mt][nt][q] = 0.f;

    for (int kc = 0; kc < 4; kc++) {
        if (kc + 1 < 4) {
            uint32_t dst = sBa + ((kc + 1) & 1) * 8448u * 4u;
            const float* src = d_W0 + (kc + 1) * 32 * 256;
            for (int i = tid; i < 2048; i += 256) {
                int rw = i >> 6, c4 = (i & 63) << 2;
                CP16(dst + (uint32_t)(rw * BS1 + c4) * 4u, src + rw * 256 + c4);
            }
            CP_COMMIT();
            CP_WAIT1();
        } else {
            CP_WAIT0();
        }
        __syncthreads();
        const uint32_t* bp = (const uint32_t*)(sB + (kc & 1) * 8448);
        const int wcb = wn * 64;
        const int ka = kc * 32;                 // A K-chunk base (fix)
#pragma unroll
        for (int ks = 0; ks < 4; ks++) {
            const int kk = ks * 8;
            uint32_t a[2][4];
#pragma unroll
            for (int mt = 0; mt < 2; mt++) {
                int rb = (wr + mt * 16 + fr) * AIS + ka + kk + fc;
                a[mt][0] = ap[rb];
                a[mt][1] = ap[rb + 8 * AIS];
                a[mt][2] = ap[rb + 4];
                a[mt][3] = ap[rb + 8 * AIS + 4];
            }
#pragma unroll
            for (int nt = 0; nt < 8; nt++) {
                uint32_t b[2];
                int bb = (kk + fc) * BS1 + wcb + nt * 8 + fr;
                b[0] = bp[bb];
                b[1] = bp[bb + 4 * BS1];
#pragma unroll
                for (int mt = 0; mt < 2; mt++) mma8(acc[mt][nt], a[mt], b);
            }
        }
        __syncthreads();
    }

#pragma unroll
    for (int mt = 0; mt < 2; mt++)
#pragma unroll
        for (int nt = 0; nt < 8; nt++) {
            int row = wr + mt * 16 + fr;
            int col = wn * 64 + nt * 8 + 2 * fc;
            *(float2*)(sU + row * US + col) = make_float2(acc[mt][nt][0], acc[mt][nt][1]);
            *(float2*)(sU + (row + 8) * US + col) = make_float2(acc[mt][nt][2], acc[mt][nt][3]);
        }
    __syncthreads();

    for (int i = tid; i < 64 * 128; i += 256) {
        int rr = i >> 7, j = i & 127;
        float f0 = sigm(sU[rr * US + j] + __ldg(Wb + j));
        float c0 = tanhf(sU[rr * US + j + 128] + __ldg(Wb + 128 + j));
        h[((size_t)batch * NN + 16383 + row0 + rr) * HD + j] = (1.f - f0) * c0;
    }
}

// --------------------------------------------------------------------------
__global__ __launch_bounds__(256) void level_small_k(
    const float* __restrict__ Ufw, const float* __restrict__ Ufb,
    const float* __restrict__ Uhw, const float* __restrict__ Uhb,
    float* __restrict__ h, int start)
{
    __shared__ float hcs[256], gs[256], fs[256], red[256];
    const int tid = threadIdx.x, batch = blockIdx.y, node = start + blockIdx.x;

    hcs[tid] = h[((size_t)batch * NN + 2 * node + 1) * HD + tid];
    __syncthreads();

    float a0 = 0.f, a1 = 0.f, a2 = 0.f, a3 = 0.f;
#pragma unroll 8
    for (int k = 0; k < 256; k += 4) {
        a0 += hcs[k]     * Ufw[(size_t)(k)     * 256 + tid];
        a1 += hcs[k + 1] * Ufw[(size_t)(k + 1) * 256 + tid];
        a2 += hcs[k + 2] * Ufw[(size_t)(k + 2) * 256 + tid];
        a3 += hcs[k + 3] * Ufw[(size_t)(k + 3) * 256 + tid];
    }
    float f = sigm((a0 + a1) + (a2 + a3) + Ufb[tid]);
    fs[tid] = f;
    gs[tid] = f * hcs[tid];
    __syncthreads();

    const int j = tid & 127, k0 = (tid >> 7) * 128;
    float b0 = 0.f, b1 = 0.f, b2 = 0.f, b3 = 0.f;
#pragma unroll 8
    for (int k = 0; k < 128; k += 4) {
        b0 += gs[k0 + k]     * Uhw[(size_t)(k0 + k)     * 128 + j];
        b1 += gs[k0 + k + 1] * Uhw[(size_t)(k0 + k + 1) * 128 + j];
        b2 += gs[k0 + k + 2] * Uhw[(size_t)(k0 + k + 2) * 128 + j];
        b3 += gs[k0 + k + 3] * Uhw[(size_t)(k0 + k + 3) * 128 + j];
    }
    red[tid] = (b0 + b1) + (b2 + b3);
    __syncthreads();

    if (tid < 128) {
        float cand = tanhf(red[tid] + red[tid + 128] + Uhb[tid]);
        float out = (1.f - fs[tid] - fs[tid + 128]) * cand + gs[tid] + gs[tid + 128];
        h[((size_t)batch * NN + node) * HD + tid] = out;
    }
}

// --------------------------------------------------------------------------
extern "C" void kernel_launch(void* const* d_in, const int* in_sizes, int n_in,
                              void* d_out, int out_size)
{
    const float* x   = (const float*)d_in[0];
    const float* Ww  = (const float*)d_in[1];
    const float* Wb  = (const float*)d_in[2];
    const float* Ufw = (const float*)d_in[3];
    const float* Ufb = (const float*)d_in[4];
    const float* Uhw = (const float*)d_in[5];
    const float* Uhb = (const float*)d_in[6];
    float* h = (float*)d_out;

    cudaFuncSetAttribute(level_mma_k, cudaFuncAttributeMaxDynamicSharedMemorySize, SMEM_LVL);
    cudaFuncSetAttribute(init_mma_k,  cudaFuncAttributeMaxDynamicSharedMemorySize, SMEM_INI);

    prep_k<<<128, 256>>>(Ww, Ufw, Uhw);
    init_mma_k<<<dim3(256, NB), 256, SMEM_INI>>>(x, Wb, h);

    for (int l = 13; l >= 0; --l) {
        int start = (1 << l) - 1, cnt = 1 << l;
        if (cnt >= 64)
            level_mma_k<<<dim3(cnt / 64, NB), 256, SMEM_LVL>>>(Ufb, Uhb, h, start);
        else
            level_small_k<<<dim3(cnt, NB), 256>>>(Ufw, Ufb, Uhw, Uhb, h, start);
    }
}

// round 6
// speedup vs baseline: 3.1257x; 1.4167x over previous
#include <cuda_runtime.h>
#include <math.h>
#include <stdint.h>

#define NB 16
#define NN 32767
#define HD 128

// tf32-rounded weight copies. d_Uf / d_W0 are COLUMN-INTERLEAVED:
//   col' = 2j   holds original col j       (A-half)
//   col' = 2j+1 holds original col 128+j   (B-half)
__device__ float d_Uf[256 * 256];
__device__ float d_Uh[256 * 128];   // not interleaved
__device__ float d_W0[128 * 256];

__device__ __forceinline__ float sigm(float v) { return 1.f / (1.f + expf(-v)); }
__device__ __forceinline__ float tf32r(float x) {
    float r; asm("cvt.rna.tf32.f32 %0, %1;" : "=f"(r) : "f"(x)); return r;
}
__device__ __forceinline__ uint32_t smem_u32(const void* p) {
    uint32_t a;
    asm("{ .reg .u64 t; cvta.to.shared.u64 t, %1; cvt.u32.u64 %0, t; }" : "=r"(a) : "l"(p));
    return a;
}
__device__ __forceinline__ void mma8(float* d, const uint32_t* a, const uint32_t* b) {
    asm volatile(
        "mma.sync.aligned.m16n8k8.row.col.f32.tf32.tf32.f32 "
        "{%0,%1,%2,%3}, {%4,%5,%6,%7}, {%8,%9}, {%0,%1,%2,%3};"
        : "+f"(d[0]), "+f"(d[1]), "+f"(d[2]), "+f"(d[3])
        : "r"(a[0]), "r"(a[1]), "r"(a[2]), "r"(a[3]), "r"(b[0]), "r"(b[1]));
}
#define CP16(daddr, sptr) \
    asm volatile("cp.async.cg.shared.global [%0], [%1], 16;" :: "r"(daddr), "l"(sptr))
#define CP_COMMIT() asm volatile("cp.async.commit_group;" ::: "memory")
#define CP_WAIT1()  asm volatile("cp.async.wait_group 1;" ::: "memory")
#define CP_WAIT0()  asm volatile("cp.async.wait_group 0;" ::: "memory")

// strides (words)
#define AS 260      // level A tile [64][256] padded
#define FS 260      // fsum/gsum [64][256] padded
#define BS1 264     // B chunk [32][256] padded
#define BS2 136     // B chunk [32][128] padded
#define AIS 132     // init A tile [64][128] padded

// level smem (floats): sA 16640 | sFG 16640 | sB 2*8448
#define L_FG 16640
#define L_SB 33280
#define SMEM_LVL ((16640 + 16640 + 2 * 8448) * 4)   // 200704 B
// init smem (floats): sA 8448 | sB 2*8448
#define I_SB 8448
#define SMEM_INI ((8448 + 2 * 8448) * 4)            // 101376 B -> 2 CTAs/SM

// --------------------------------------------------------------------------
__global__ void prep_k(const float* __restrict__ Ww, const float* __restrict__ Ufw,
                       const float* __restrict__ Uhw)
{
    int i0 = blockIdx.x * blockDim.x + threadIdx.x, st = gridDim.x * blockDim.x;
    for (int idx = i0; idx < 131072; idx += st) {
        if (idx < 65536) {
            int k = idx >> 8, c = idx & 255;
            d_Uf[idx] = tf32r(Ufw[k * 256 + (c >> 1) + ((c & 1) << 7)]);
        } else if (idx < 98304) {
            d_Uh[idx - 65536] = tf32r(Uhw[idx - 65536]);
        } else {
            int j = idx - 98304, k = j >> 8, c = j & 255;
            d_W0[j] = tf32r(Ww[k * 256 + (c >> 1) + ((c & 1) << 7)]);
        }
    }
}

// --------------------------------------------------------------------------
// Level kernel: 64 parents/CTA, 512 threads (16 warps, 2M x 8N).
// --------------------------------------------------------------------------
__global__ __launch_bounds__(512, 1) void level_mma_k(
    const float* __restrict__ Ufb, const float* __restrict__ Uhb,
    float* __restrict__ h, int start)
{
    extern __shared__ float sm[];
    float* sA  = sm;
    float* sFG = sm + L_FG;
    float* sB  = sm + L_SB;
    const uint32_t sBa = smem_u32(sB);

    const int tid = threadIdx.x, lane = tid & 31, wid = tid >> 5;
    const int batch = blockIdx.y;
    const int node0 = start + blockIdx.x * 64;
    const float* hcg = h + ((size_t)batch * NN + 2 * node0 + 1) * HD;

    // prefetch B1 chunk 0
    for (int i = tid; i < 2048; i += 512) {
        int rw = i >> 6, c4 = (i & 63) << 2;
        CP16(sBa + (uint32_t)(rw * BS1 + c4) * 4u, d_Uf + rw * 256 + c4);
    }
    CP_COMMIT();

    // load A = hc tile (64 x 256), tf32-rounded
    for (int i = tid; i < 4096; i += 512) {
        float4 v = ((const float4*)hcg)[i];
        int r = i >> 6, c = (i & 63) << 2;
        *(float4*)(sA + r * AS + c) =
            make_float4(tf32r(v.x), tf32r(v.y), tf32r(v.z), tf32r(v.w));
    }

    const int wm = wid & 1, wn = wid >> 1;       // wn 0..7
    const int wr = wm * 32;
    const int fr = lane >> 2, fc = lane & 3;
    const uint32_t* ap = (const uint32_t*)sA;

    // ---------------- phase 1: u = hc @ Uf (interleaved cols) ----------------
    float acc[2][4][4];
#pragma unroll
    for (int mt = 0; mt < 2; mt++)
#pragma unroll
        for (int nt = 0; nt < 4; nt++)
#pragma unroll
            for (int q = 0; q < 4; q++) acc[mt][nt][q] = 0.f;

    for (int kc = 0; kc < 8; kc++) {
        if (kc + 1 < 8) {
            uint32_t dst = sBa + ((kc + 1) & 1) * 8448u * 4u;
            const float* src = d_Uf + (kc + 1) * 32 * 256;
            for (int i = tid; i < 2048; i += 512) {
                int rw = i >> 6, c4 = (i & 63) << 2;
                CP16(dst + (uint32_t)(rw * BS1 + c4) * 4u, src + rw * 256 + c4);
            }
            CP_COMMIT();
            CP_WAIT1();
        } else {
            CP_WAIT0();
        }
        __syncthreads();
        const uint32_t* bp = (const uint32_t*)(sB + (kc & 1) * 8448);
        const int wcb = wn * 32;          // interleaved col base
        const int ka = kc * 32;
#pragma unroll
        for (int ks = 0; ks < 4; ks++) {
            const int kk = ks * 8;
            uint32_t a[2][4];
#pragma unroll
            for (int mt = 0; mt < 2; mt++) {
                int rb = (wr + mt * 16 + fr) * AS + ka + kk + fc;
                a[mt][0] = ap[rb];
                a[mt][1] = ap[rb + 8 * AS];
                a[mt][2] = ap[rb + 4];
                a[mt][3] = ap[rb + 8 * AS + 4];
            }
#pragma unroll
            for (int nt = 0; nt < 4; nt++) {
                uint32_t b[2];
                int bb = (kk + fc) * BS1 + wcb + nt * 8 + fr;
                b[0] = bp[bb];
                b[1] = bp[bb + 4 * BS1];
#pragma unroll
                for (int mt = 0; mt < 2; mt++) mma8(acc[mt][nt], a[mt], b);
            }
        }
        __syncthreads();
    }

    // prefetch B2 chunk 0 (overlaps epilogue 1); buffers free after final sync
    for (int i = tid; i < 1024; i += 512) {
        int rw = i >> 5, c4 = (i & 31) << 2;
        CP16(sBa + (uint32_t)(rw * BS2 + c4) * 4u, d_Uh + rw * 128 + c4);
    }
    CP_COMMIT();

    // ---------------- epilogue 1 (registers) ----------------
    // d0,d1 = (uA(j), uB(j)) thanks to the interleaved Uf columns.
#pragma unroll
    for (int mt = 0; mt < 2; mt++)
#pragma unroll
        for (int nt = 0; nt < 4; nt++) {
            const int j = wn * 16 + nt * 4 + fc;
            const float bfA = __ldg(Ufb + j), bfB = __ldg(Ufb + 128 + j);
#pragma unroll
            for (int half = 0; half < 2; half++) {
                int r = wr + mt * 16 + fr + half * 8;
                float uA = acc[mt][nt][half * 2];
                float uB = acc[mt][nt][half * 2 + 1];
                float fA = sigm(uA + bfA);
                float fB = sigm(uB + bfB);
                float hA = __ldg(hcg + r * 256 + j);
                float hB = __ldg(hcg + r * 256 + 128 + j);
                float gA = fA * hA, gB = fB * hB;
                sA[r * AS + j]        = tf32r(gA);
                sA[r * AS + 128 + j]  = tf32r(gB);
                sFG[r * FS + j]       = fA + fB;   // fsum
                sFG[r * FS + 128 + j] = gA + gB;   // gsum (exact fp32)
            }
        }

    // ---------------- phase 2: v = g @ Uh ----------------
    float ac2[2][2][4];
#pragma unroll
    for (int mt = 0; mt < 2; mt++)
#pragma unroll
        for (int nt = 0; nt < 2; nt++)
#pragma unroll
            for (int q = 0; q < 4; q++) ac2[mt][nt][q] = 0.f;

    for (int kc = 0; kc < 8; kc++) {
        if (kc + 1 < 8) {
            uint32_t dst = sBa + ((kc + 1) & 1) * 8448u * 4u;
            const float* src = d_Uh + (kc + 1) * 32 * 128;
            for (int i = tid; i < 1024; i += 512) {
                int rw = i >> 5, c4 = (i & 31) << 2;
                CP16(dst + (uint32_t)(rw * BS2 + c4) * 4u, src + rw * 128 + c4);
            }
            CP_COMMIT();
            CP_WAIT1();
        } else {
            CP_WAIT0();
        }
        __syncthreads();   // first iteration also orders epilogue-1 smem writes
        const uint32_t* bp = (const uint32_t*)(sB + (kc & 1) * 8448);
        const int ka = kc * 32;
#pragma unroll
        for (int ks = 0; ks < 4; ks++) {
            const int kk = ks * 8;
            uint32_t a[2][4];
#pragma unroll
            for (int mt = 0; mt < 2; mt++) {
                int rb = (wr + mt * 16 + fr) * AS + ka + kk + fc;
                a[mt][0] = ap[rb];
                a[mt][1] = ap[rb + 8 * AS];
                a[mt][2] = ap[rb + 4];
                a[mt][3] = ap[rb + 8 * AS + 4];
            }
#pragma unroll
            for (int nt = 0; nt < 2; nt++) {
                uint32_t b[2];
                int bb = (kk + fc) * BS2 + wn * 16 + nt * 8 + fr;
                b[0] = bp[bb];
                b[1] = bp[bb + 4 * BS2];
#pragma unroll
                for (int mt = 0; mt < 2; mt++) mma8(ac2[mt][nt], a[mt], b);
            }
        }
        __syncthreads();
    }

    // ---------------- epilogue 2 ----------------
#pragma unroll
    for (int mt = 0; mt < 2; mt++)
#pragma unroll
        for (int nt = 0; nt < 2; nt++) {
            int lr0 = wr + mt * 16 + fr;
            int lr1 = lr0 + 8;
            int col = wn * 16 + nt * 8 + 2 * fc;
            float bh0 = __ldg(Uhb + col), bh1 = __ldg(Uhb + col + 1);
            const float* a = ac2[mt][nt];
            float o00 = (1.f - sFG[lr0 * FS + col])     * tanhf(a[0] + bh0) + sFG[lr0 * FS + col + 128];
            float o01 = (1.f - sFG[lr0 * FS + col + 1]) * tanhf(a[1] + bh1) + sFG[lr0 * FS + col + 129];
            float o10 = (1.f - sFG[lr1 * FS + col])     * tanhf(a[2] + bh0) + sFG[lr1 * FS + col + 128];
            float o11 = (1.f - sFG[lr1 * FS + col + 1]) * tanhf(a[3] + bh1) + sFG[lr1 * FS + col + 129];
            float* outp = h + ((size_t)batch * NN + node0 + lr0) * HD + col;
            *(float2*)outp = make_float2(o00, o01);
            *(float2*)(outp + 8 * HD) = make_float2(o10, o11);
        }
}

// --------------------------------------------------------------------------
// Init kernel: 64 leaf rows/CTA, 512 threads, interleaved W0, smem 101KB
// (2 CTAs/SM). Output staged through sA for coalesced stores.
// --------------------------------------------------------------------------
__global__ __launch_bounds__(512) void init_mma_k(
    const float* __restrict__ x, const float* __restrict__ Wb, float* __restrict__ h)
{
    extern __shared__ float sm[];
    float* sA = sm;
    float* sB = sm + I_SB;
    const uint32_t sBa = smem_u32(sB);

    const int tid = threadIdx.x, lane = tid & 31, wid = tid >> 5;
    const int batch = blockIdx.y;
    const int row0 = blockIdx.x * 64;   // leaf-local
    const float* xg = x + ((size_t)batch * NN + 16383 + row0) * HD;

    // prefetch W chunk 0 (full [32][256] = 2048 float4)
    for (int i = tid; i < 2048; i += 512) {
        int rw = i >> 6, c4 = (i & 63) << 2;
        CP16(sBa + (uint32_t)(rw * BS1 + c4) * 4u, d_W0 + rw * 256 + c4);
    }
    CP_COMMIT();

    for (int i = tid; i < 2048; i += 512) {
        float4 v = ((const float4*)xg)[i];
        int r = i >> 5, c = (i & 31) << 2;
        *(float4*)(sA + r * AIS + c) =
            make_float4(tf32r(v.x), tf32r(v.y), tf32r(v.z), tf32r(v.w));
    }

    const int wm = wid & 1, wn = wid >> 1;
    const int wr = wm * 32;
    const int fr = lane >> 2, fc = lane & 3;
    const uint32_t* ap = (const uint32_t*)sA;

    float acc[2][4][4];
#pragma unroll
    for (int mt = 0; mt < 2; mt++)
#pragma unroll
        for (int nt = 0; nt < 4; nt++)
#pragma unroll
            for (int q = 0; q < 4; q++) acc[mt][nt][q] = 0.f;

    for (int kc = 0; kc < 4; kc++) {
        if (kc + 1 < 4) {
            uint32_t dst = sBa + ((kc + 1) & 1) * 8448u * 4u;
            const float* src = d_W0 + (kc + 1) * 32 * 256;
            for (int i = tid; i < 2048; i += 512) {
                int rw = i >> 6, c4 = (i & 63) << 2;
                CP16(dst + (uint32_t)(rw * BS1 + c4) * 4u, src + rw * 256 + c4);
            }
            CP_COMMIT();
            CP_WAIT1();
        } else {
            CP_WAIT0();
        }
        __syncthreads();
        const uint32_t* bp = (const uint32_t*)(sB + (kc & 1) * 8448);
        const int wcb = wn * 32;
        const int ka = kc * 32;
#pragma unroll
        for (int ks = 0; ks < 4; ks++) {
            const int kk = ks * 8;
            uint32_t a[2][4];
#pragma unroll
            for (int mt = 0; mt < 2; mt++) {
                int rb = (wr + mt * 16 + fr) * AIS + ka + kk + fc;
                a[mt][0] = ap[rb];
                a[mt][1] = ap[rb + 8 * AIS];
                a[mt][2] = ap[rb + 4];
                a[mt][3] = ap[rb + 8 * AIS + 4];
            }
#pragma unroll
            for (int nt = 0; nt < 4; nt++) {
                uint32_t b[2];
                int bb = (kk + fc) * BS1 + wcb + nt * 8 + fr;
                b[0] = bp[bb];
                b[1] = bp[bb + 4 * BS1];
#pragma unroll
                for (int mt = 0; mt < 2; mt++) mma8(acc[mt][nt], a[mt], b);
            }
        }
        __syncthreads();
    }

    // epilogue in registers -> stage to sA (dead) for coalesced write
#pragma unroll
    for (int mt = 0; mt < 2; mt++)
#pragma unroll
        for (int nt = 0; nt < 4; nt++) {
            const int j = wn * 16 + nt * 4 + fc;
            const float bA = __ldg(Wb + j), bB = __ldg(Wb + 128 + j);
#pragma unroll
            for (int half = 0; half < 2; half++) {
                int r = wr + mt * 16 + fr + half * 8;
                float f0 = sigm(acc[mt][nt][half * 2] + bA);
                float c0 = tanhf(acc[mt][nt][half * 2 + 1] + bB);
                sA[r * AIS + j] = (1.f - f0) * c0;
            }
        }
    __syncthreads();

    for (int i = tid; i < 2048; i += 512) {
        int r = i >> 5, c = (i & 31) << 2;
        float4 v = *(const float4*)(sA + r * AIS + c);
        *(float4*)(h + ((size_t)batch * NN + 16383 + row0 + r) * HD + c) = v;
    }
}

// --------------------------------------------------------------------------
__global__ __launch_bounds__(256) void level_small_k(
    const float* __restrict__ Ufw, const float* __restrict__ Ufb,
    const float* __restrict__ Uhw, const float* __restrict__ Uhb,
    float* __restrict__ h, int start)
{
    __shared__ float hcs[256], gs[256], fs[256], red[256];
    const int tid = threadIdx.x, batch = blockIdx.y, node = start + blockIdx.x;

    hcs[tid] = h[((size_t)batch * NN + 2 * node + 1) * HD + tid];
    __syncthreads();

    float a0 = 0.f, a1 = 0.f, a2 = 0.f, a3 = 0.f;
#pragma unroll 8
    for (int k = 0; k < 256; k += 4) {
        a0 += hcs[k]     * Ufw[(size_t)(k)     * 256 + tid];
        a1 += hcs[k + 1] * Ufw[(size_t)(k + 1) * 256 + tid];
        a2 += hcs[k + 2] * Ufw[(size_t)(k + 2) * 256 + tid];
        a3 += hcs[k + 3] * Ufw[(size_t)(k + 3) * 256 + tid];
    }
    float f = sigm((a0 + a1) + (a2 + a3) + Ufb[tid]);
    fs[tid] = f;
    gs[tid] = f * hcs[tid];
    __syncthreads();

    const int j = tid & 127, k0 = (tid >> 7) * 128;
    float b0 = 0.f, b1 = 0.f, b2 = 0.f, b3 = 0.f;
#pragma unroll 8
    for (int k = 0; k < 128; k += 4) {
        b0 += gs[k0 + k]     * Uhw[(size_t)(k0 + k)     * 128 + j];
        b1 += gs[k0 + k + 1] * Uhw[(size_t)(k0 + k + 1) * 128 + j];
        b2 += gs[k0 + k + 2] * Uhw[(size_t)(k0 + k + 2) * 128 + j];
        b3 += gs[k0 + k + 3] * Uhw[(size_t)(k0 + k + 3) * 128 + j];
    }
    red[tid] = (b0 + b1) + (b2 + b3);
    __syncthreads();

    if (tid < 128) {
        float cand = tanhf(red[tid] + red[tid + 128] + Uhb[tid]);
        float out = (1.f - fs[tid] - fs[tid + 128]) * cand + gs[tid] + gs[tid + 128];
        h[((size_t)batch * NN + node) * HD + tid] = out;
    }
}

// --------------------------------------------------------------------------
extern "C" void kernel_launch(void* const* d_in, const int* in_sizes, int n_in,
                              void* d_out, int out_size)
{
    const float* x   = (const float*)d_in[0];
    const float* Ww  = (const float*)d_in[1];
    const float* Wb  = (const float*)d_in[2];
    const float* Ufw = (const float*)d_in[3];
    const float* Ufb = (const float*)d_in[4];
    const float* Uhw = (const float*)d_in[5];
    const float* Uhb = (const float*)d_in[6];
    float* h = (float*)d_out;

    cudaFuncSetAttribute(level_mma_k, cudaFuncAttributeMaxDynamicSharedMemorySize, SMEM_LVL);
    cudaFuncSetAttribute(init_mma_k,  cudaFuncAttributeMaxDynamicSharedMemorySize, SMEM_INI);

    prep_k<<<128, 256>>>(Ww, Ufw, Uhw);
    init_mma_k<<<dim3(256, NB), 512, SMEM_INI>>>(x, Wb, h);

    for (int l = 13; l >= 0; --l) {
        int start = (1 << l) - 1, cnt = 1 << l;
        if (cnt >= 64)
            level_mma_k<<<dim3(cnt / 64, NB), 512, SMEM_LVL>>>(Ufb, Uhb, h, start);
        else
            level_small_k<<<dim3(cnt, NB), 256>>>(Ufw, Ufb, Uhw, Uhb, h, start);
    }
}